// round 17
// baseline (speedup 1.0000x reference)
#include <cuda_runtime.h>
#include <cstdint>

#define BATCH 8
#define NPTS  32768
#define SPTS  512
#define GRP   32
#define BIGF  1e10f
#define R2F   0.04f

#define CLUSTER      8
#define THREADS      128
#define FPS_NWARP    (THREADS / 32)          // 4
#define NSLOT        (CLUSTER * FPS_NWARP)   // 32
#define PTS_BLK      (NPTS / CLUSTER)        // 4096
#define PPT          (PTS_BLK / THREADS)     // 32
#define NP2          (PPT / 2)               // 16 packed slots

#define CPT2       8                          // centroids per ball CTA
#define CHUNKS     (SPTS / CPT2)              // 64
#define BALL_CTAS  (BATCH * CHUNKS)           // 512
#define FPS_CTAS   (BATCH * CLUSTER)          // 64
#define TOTAL_CTAS (FPS_CTAS + BALL_CTAS)     // 576
#define CAP        128

#define COMB_ELEMS (BATCH * SPTS * (GRP + 1) * 3)  // 405504
#define DSMEM_REQ  (120 * 1024)               // >= 64KB stage; forces 1 CTA/SM

__device__ float4  g_xyz4[BATCH * NPTS];
__device__ unsigned g_cnt[BATCH];             // centroids-ready counters (zero-init)
__device__ unsigned g_done;                   // ball completion counter

// ---------------------------------------------------------------------------
// helpers
// ---------------------------------------------------------------------------
__device__ __forceinline__ unsigned smem_u32(const void* p) {
    unsigned a;
    asm("{ .reg .u64 t; cvta.to.shared.u64 t, %1; cvt.u32.u64 %0, t; }" : "=r"(a) : "l"(p));
    return a;
}
__device__ __forceinline__ unsigned redux_max_u32(unsigned v) {
    unsigned r; asm("redux.sync.max.u32 %0, %1, 0xffffffff;" : "=r"(r) : "r"(v)); return r;
}
__device__ __forceinline__ unsigned redux_min_u32(unsigned v) {
    unsigned r; asm("redux.sync.min.u32 %0, %1, 0xffffffff;" : "=r"(r) : "r"(v)); return r;
}
__device__ __forceinline__ unsigned mapa_u32(unsigned laddr, unsigned rank) {
    unsigned r; asm("mapa.shared::cluster.u32 %0, %1, %2;" : "=r"(r) : "r"(laddr), "r"(rank));
    return r;
}

// packed f32x2 (Blackwell): IEEE rn per component — bit-identical to scalar rn
#define PACK2(d, lo, hi)  asm("mov.b64 %0, {%1, %2};" : "=l"(d) : "f"(lo), "f"(hi))
#define UNPACK2(lo, hi, s) asm("mov.b64 {%0, %1}, %2;" : "=f"(lo), "=f"(hi) : "l"(s))
#define ADD2(d, a, b) asm("add.rn.f32x2 %0, %1, %2;" : "=l"(d) : "l"(a), "l"(b))
#define MUL2(d, a, b) asm("mul.rn.f32x2 %0, %1, %2;" : "=l"(d) : "l"(a), "l"(b))

__device__ __forceinline__ float negf(float a) {
    return __uint_as_float(__float_as_uint(a) ^ 0x80000000u);
}

#define MBAR_INIT(addr, cnt) \
    asm volatile("mbarrier.init.shared.b64 [%0], %1;" :: "r"(addr), "r"(cnt) : "memory")

#define MBAR_EXPECT_TX(addr, bytes) \
    asm volatile("mbarrier.arrive.expect_tx.shared.b64 _, [%0], %1;" \
                 :: "r"(addr), "r"(bytes) : "memory")

#define ST_ASYNC_U64(rslot, val, rbar) \
    asm volatile("st.async.shared::cluster.mbarrier::complete_tx::bytes.b64 [%0], %1, [%2];" \
                 :: "r"(rslot), "l"(val), "r"(rbar) : "memory")

#define ST_ASYNC_V2U64(rslot, v0, v1, rbar) \
    asm volatile("st.async.shared::cluster.mbarrier::complete_tx::bytes.v2.b64 [%0], {%1, %2}, [%3];" \
                 :: "r"(rslot), "l"(v0), "l"(v1), "r"(rbar) : "memory")

#define MBAR_WAIT_PARITY_ACQ_CLUSTER(mbar, parity) do {                            \
    unsigned _m = (mbar), _p = (parity), _d;                                       \
    asm volatile("{\n\t.reg .pred p;\n\t"                                          \
        "mbarrier.try_wait.parity.acquire.cluster.shared::cta.b64 p, [%1], %2;\n\t"\
        "selp.b32 %0, 1, 0, p;\n\t}"                                               \
        : "=r"(_d) : "r"(_m), "r"(_p) : "memory");                                 \
    if (!_d) {                                                                     \
        asm volatile("{\n\t.reg .pred P1;\n"                                       \
            "WL_%=:\n\t"                                                           \
            "mbarrier.try_wait.parity.acquire.cluster.shared::cta.b64 P1, [%0], %1;\n\t" \
            "@P1 bra.uni WD_%=;\n\t"                                               \
            "bra.uni WL_%=;\n"                                                     \
            "WD_%=:\n\t}" :: "r"(_m), "r"(_p) : "memory");                         \
    }                                                                              \
} while (0)

#define CLUSTER_SYNC_ASM() do {                                        \
    asm volatile("barrier.cluster.arrive.aligned;" ::: "memory");      \
    asm volatile("barrier.cluster.wait.aligned;" ::: "memory");        \
} while (0)

struct __align__(16) XSlot { unsigned long long key, xy, zw, pad; };

// ---------------------------------------------------------------------------
// FPS role (bid < 64): R16 pipeline + xyz staging (absorbs pad) + progress
// counter release every CPT2 iterations.
// ---------------------------------------------------------------------------
__device__ void fps_role(const float* __restrict__ xyz,
                         const int* __restrict__ finit,
                         float* __restrict__ out_cent,
                         int bid) {
    extern __shared__ float4 stage[];     // [PTS_BLK] this CTA's points
    const int tid  = threadIdx.x;
    const int lane = tid & 31, wid = tid >> 5;
    unsigned rank;
    asm("mov.u32 %0, %%cluster_ctarank;" : "=r"(rank));
    const int b = bid / CLUSTER;

    __shared__ XSlot cslot[2][NSLOT];
    __shared__ unsigned long long bars[2];

    if (tid == 0) {
        MBAR_INIT(smem_u32(&bars[0]), 1);
        MBAR_INIT(smem_u32(&bars[1]), 1);
        MBAR_EXPECT_TX(smem_u32(&bars[0]), 24u * NSLOT);
        MBAR_EXPECT_TX(smem_u32(&bars[1]), 24u * NSLOT);
    }

    // stage this CTA's partition from xyz (also writes g_xyz4 for ball CTAs)
    const int pbase = rank * PTS_BLK;
    for (int i = tid; i < PTS_BLK; i += THREADS) {
        int g = b * NPTS + pbase + i;
        float4 v = make_float4(xyz[3 * g], xyz[3 * g + 1], xyz[3 * g + 2], 0.f);
        stage[i] = v;
        g_xyz4[g] = v;
    }

    __syncthreads();
    CLUSTER_SYNC_ASM();   // barriers + staging visible cluster-wide

    unsigned long long pxx[NP2], pyy[NP2], pzz[NP2];
    float dd[PPT];
    const int pid0 = pbase + tid;
#pragma unroll
    for (int j = 0; j < NP2; j++) {
        float4 a = stage[tid + (2 * j) * THREADS];
        float4 c = stage[tid + (2 * j + 1) * THREADS];
        PACK2(pxx[j], a.x, c.x);
        PACK2(pyy[j], a.y, c.y);
        PACK2(pzz[j], a.z, c.z);
        dd[2 * j] = BIGF; dd[2 * j + 1] = BIGF;
    }

    const unsigned lslot0 = smem_u32(&cslot[0][rank * FPS_NWARP + wid]);
    const unsigned lslot1 = smem_u32(&cslot[1][rank * FPS_NWARP + wid]);
    const unsigned lbar0  = smem_u32(&bars[0]);
    const unsigned lbar1  = smem_u32(&bars[1]);
    const unsigned tr     = (unsigned)(lane & 7);
    const unsigned rslot0 = mapa_u32(lslot0, tr);
    const unsigned rslot1 = mapa_u32(lslot1, tr);
    const unsigned rbar0  = mapa_u32(lbar0, tr);
    const unsigned rbar1  = mapa_u32(lbar1, tr);
    const unsigned stage_base = smem_u32(&stage[0]);

    // initial centroid from xyz (input, no same-kernel write hazard)
    float cx, cy, cz;
    {
        int gi = b * NPTS + finit[b];
        cx = xyz[3 * gi]; cy = xyz[3 * gi + 1]; cz = xyz[3 * gi + 2];
    }

    for (int s = 0; s < SPTS; s++) {
        if (rank == 0 && tid == 0) {
            float* o = out_cent + (size_t)(b * SPTS + s) * 3;
            o[0] = cx; o[1] = cy; o[2] = cz;
            if (((s + 1) & (CPT2 - 1)) == 0) {   // every 8th: publish progress
                asm volatile("st.release.gpu.global.u32 [%0], %1;"
                             :: "l"(&g_cnt[b]), "r"((unsigned)(s + 1)) : "memory");
            }
        }
        if (s == SPTS - 1) break;

        unsigned long long ncx2, ncy2, ncz2;
        {
            float nx = negf(cx), ny = negf(cy), nz = negf(cz);
            PACK2(ncx2, nx, nx); PACK2(ncy2, ny, ny); PACK2(ncz2, nz, nz);
        }
        float bv = -1.f;
#pragma unroll
        for (int j = 0; j < NP2; j++) {
            unsigned long long dx2, dy2, dz2, s2;
            ADD2(dx2, pxx[j], ncx2);
            ADD2(dy2, pyy[j], ncy2);
            ADD2(dz2, pzz[j], ncz2);
            MUL2(dx2, dx2, dx2);
            MUL2(dy2, dy2, dy2);
            MUL2(dz2, dz2, dz2);
            ADD2(s2, dx2, dy2);
            ADD2(s2, s2, dz2);
            float lo, hi; UNPACK2(lo, hi, s2);
            float n0 = fminf(dd[2 * j], lo);
            float n1 = fminf(dd[2 * j + 1], hi);
            dd[2 * j] = n0; dd[2 * j + 1] = n1;
            bv = fmaxf(bv, n0);
            bv = fmaxf(bv, n1);
        }

        unsigned m = 0;
#pragma unroll
        for (int i = 0; i < PPT; i++) m |= (dd[i] == bv) ? (1u << i) : 0u;
        int bi = __ffs(m) - 1;
        unsigned bpid = (unsigned)(pid0 + bi * THREADS);

        unsigned vb   = __float_as_uint(bv);
        unsigned vmax = redux_max_u32(vb);
        unsigned pidw = redux_min_u32((vb == vmax) ? bpid : 0xffffffffu);

        const int bb = s & 1;
        const unsigned ph = (unsigned)((s >> 1) & 1);

        if (lane < CLUSTER) {
            unsigned off = pidw & (PTS_BLK - 1);
            unsigned long long wxy, wzw;
            asm volatile("ld.shared.v2.b64 {%0, %1}, [%2];"
                         : "=l"(wxy), "=l"(wzw) : "r"(stage_base + off * 16u));
            unsigned long long key = ((unsigned long long)vmax << 32) | pidw;
            unsigned rs = bb ? rslot1 : rslot0;
            unsigned rb = bb ? rbar1  : rbar0;
            ST_ASYNC_V2U64(rs,      key, wxy, rb);
            ST_ASYNC_U64(rs + 16u,  wzw, rb);
        }

        const unsigned lbar = bb ? lbar1 : lbar0;
        MBAR_WAIT_PARITY_ACQ_CLUSTER(lbar, ph);

        if (tid == 0)
            MBAR_EXPECT_TX(lbar, 24u * NSLOT);

        unsigned long long ck = cslot[bb][lane].key;
        unsigned cv  = (unsigned)(ck >> 32);
        unsigned cp  = (unsigned)ck;
        unsigned cvm = redux_max_u32(cv);
        unsigned cpm = redux_min_u32((cv == cvm) ? cp : 0xffffffffu);
        unsigned mk  = __ballot_sync(0xffffffffu, cp == cpm && cv == cvm);
        int src = __ffs(mk) - 1;

        unsigned long long wxy = cslot[bb][src].xy;
        unsigned long long wzw = cslot[bb][src].zw;
        cx = __uint_as_float((unsigned)wxy);
        cy = __uint_as_float((unsigned)(wxy >> 32));
        cz = __uint_as_float((unsigned)wzw);
    }

    CLUSTER_SYNC_ASM();   // keep smem staging alive until all CTAs done
}

// ---------------------------------------------------------------------------
// Ball role (bid >= 64): waits for its 8 centroids, then proven ball pipeline
// (collection / split-redux selection / index-ordered padding / output).
// ---------------------------------------------------------------------------
__device__ void ball_role(const float* __restrict__ cent,
                          float* __restrict__ outc,
                          int bid) {
    const int bb2   = bid - FPS_CTAS;
    const int batch = bb2 & (BATCH - 1);
    const int s0    = (bb2 >> 3) * CPT2;       // chunk index * 8
    const int tid   = threadIdx.x;
    const int lane  = tid & 31, wid = tid >> 5;

    __shared__ float4 sc[CPT2];
    __shared__ int cnt[CPT2];
    __shared__ unsigned long long keys[CPT2][CAP];
    __shared__ int sel[CPT2][GRP];

    // wait until centroids [s0, s0+8) are published
    if (tid == 0) {
        const unsigned need = (unsigned)(s0 + CPT2);
        unsigned v;
        for (;;) {
            asm volatile("ld.acquire.gpu.global.u32 %0, [%1];"
                         : "=r"(v) : "l"(&g_cnt[batch]) : "memory");
            if (v >= need) break;
            __nanosleep(256);
        }
    }
    __syncthreads();   // acquire by tid0 + barrier orders all threads' reads

    if (tid < CPT2) {
        cnt[tid] = 0;
        const float* c = cent + (size_t)(batch * SPTS + s0 + tid) * 3;
        // .cg loads: bypass L1 (lines may be stale from a prior CTA on this SM)
        sc[tid] = make_float4(__ldcg(c), __ldcg(c + 1), __ldcg(c + 2), 0.f);
    }
    __syncthreads();

    unsigned long long ncx2[CPT2 / 2], ncy2[CPT2 / 2], ncz2[CPT2 / 2];
#pragma unroll
    for (int j = 0; j < CPT2 / 2; j++) {
        float4 a = sc[2 * j], c = sc[2 * j + 1];
        PACK2(ncx2[j], negf(a.x), negf(c.x));
        PACK2(ncy2[j], negf(a.y), negf(c.y));
        PACK2(ncz2[j], negf(a.z), negf(c.z));
    }

    const float4* __restrict__ xb = g_xyz4 + batch * NPTS;

#pragma unroll 2
    for (int pid = tid; pid < NPTS; pid += THREADS) {
        float4 p = xb[pid];
        unsigned long long px2, py2, pz2;
        PACK2(px2, p.x, p.x); PACK2(py2, p.y, p.y); PACK2(pz2, p.z, p.z);
#pragma unroll
        for (int j = 0; j < CPT2 / 2; j++) {
            unsigned long long dx2, dy2, dz2, s2;
            ADD2(dx2, px2, ncx2[j]);
            ADD2(dy2, py2, ncy2[j]);
            ADD2(dz2, pz2, ncz2[j]);
            MUL2(dx2, dx2, dx2);
            MUL2(dy2, dy2, dy2);
            MUL2(dz2, dz2, dz2);
            ADD2(s2, dx2, dy2);
            ADD2(s2, s2, dz2);
            float lo, hi; UNPACK2(lo, hi, s2);
            if (lo <= R2F) {
                int pos = atomicAdd(&cnt[2 * j], 1);
                if (pos < CAP)
                    keys[2 * j][pos] = ((unsigned long long)__float_as_uint(lo) << 32) | (unsigned)pid;
            }
            if (hi <= R2F) {
                int pos = atomicAdd(&cnt[2 * j + 1], 1);
                if (pos < CAP)
                    keys[2 * j + 1][pos] = ((unsigned long long)__float_as_uint(hi) << 32) | (unsigned)pid;
            }
        }
    }
    __syncthreads();

    // selection: 4 warps x 2 centroids each
    for (int k = 0; k < CPT2 / FPS_NWARP; k++) {
        const int c = wid * (CPT2 / FPS_NWARP) + k;
        const int m = min(cnt[c], CAP);
        const int K = min(m, GRP);

        unsigned long long kk[CAP / 32];
#pragma unroll
        for (int j = 0; j < CAP / 32; j++) {
            int pos = lane + 32 * j;
            kk[j] = (pos < m) ? keys[c][pos] : 0xFFFFFFFFFFFFFFFFull;
        }
        for (int t = 0; t < K; t++) {
            unsigned long long lmin = kk[0];
#pragma unroll
            for (int j = 1; j < CAP / 32; j++) lmin = (kk[j] < lmin) ? kk[j] : lmin;
            unsigned ld = (unsigned)(lmin >> 32);
            unsigned lp = (unsigned)lmin;
            unsigned dmin = redux_min_u32(ld);
            unsigned pidm = redux_min_u32((ld == dmin) ? lp : 0xffffffffu);
            unsigned long long lm = ((unsigned long long)dmin << 32) | pidm;
#pragma unroll
            for (int j = 0; j < CAP / 32; j++) if (kk[j] == lm) kk[j] = 0xFFFFFFFFFFFFFFFFull;
            if (lane == 0) sel[c][t] = (int)pidm;
        }

        float ccx, ccy, ccz;
        { float4 t4 = sc[c]; ccx = t4.x; ccy = t4.y; ccz = t4.z; }
        int need = GRP - K;
        int base = 0;
        while (need > 0) {
            int id = base + lane;
            bool oor = false;
            if (id < NPTS) {
                float4 p = xb[id];
                float dx = p.x - ccx, dy = p.y - ccy, dz = p.z - ccz;
                float sq = __fadd_rn(__fadd_rn(__fmul_rn(dx, dx), __fmul_rn(dy, dy)),
                                     __fmul_rn(dz, dz));
                oor = (sq > R2F);
            }
            unsigned msk = __ballot_sync(0xffffffffu, oor);
            int r = __popc(msk & ((1u << lane) - 1u));
            if (oor && r < need) sel[c][GRP - need + r] = id;
            int take = min(__popc(msk), need);
            need -= take;
            base += 32;
        }
    }
    __syncthreads();

    for (int k = 0; k < CPT2 / FPS_NWARP; k++) {
        const int c = wid * (CPT2 / FPS_NWARP) + k;
        const int s = s0 + c;
        float4 cc = sc[c];
        float* ob = outc + (size_t)((batch * SPTS + s) * (GRP + 1)) * 3;
        if (lane == 0) { ob[0] = cc.x; ob[1] = cc.y; ob[2] = cc.z; }
        int idx = sel[c][lane];
        float4 p = xb[idx];
        float* og = ob + (size_t)(1 + lane) * 3;
        og[0] = p.x - cc.x; og[1] = p.y - cc.y; og[2] = p.z - cc.z;
    }
    __syncthreads();

    // last ball CTA to finish resets the progress flags (no one still spins:
    // all 512 ball CTAs have passed their waits before the 512th finishes)
    if (tid == 0) {
        unsigned old = atomicAdd(&g_done, 1);
        if (old == BALL_CTAS - 1) {
#pragma unroll
            for (int i = 0; i < BATCH; i++) g_cnt[i] = 0;
            g_done = 0;
        }
    }
}

// ---------------------------------------------------------------------------
__global__ void __cluster_dims__(CLUSTER, 1, 1) __launch_bounds__(THREADS, 1)
fused_kernel(const float* __restrict__ xyz, const int* __restrict__ finit,
             float* __restrict__ cent, float* __restrict__ comb) {
    if (blockIdx.x < FPS_CTAS)
        fps_role(xyz, finit, cent, blockIdx.x);
    else
        ball_role(cent, comb, blockIdx.x);
}

// ---------------------------------------------------------------------------
extern "C" void kernel_launch(void* const* d_in, const int* in_sizes, int n_in,
                              void* d_out, int out_size) {
    const float* xyz   = (const float*)d_in[0];
    const int*   finit = (const int*)d_in[1];
    float* out  = (float*)d_out;
    float* comb = out;                 // [B,S,33,3]
    float* cent = out + COMB_ELEMS;    // [B,S,3]

    cudaFuncSetAttribute(fused_kernel, cudaFuncAttributeMaxDynamicSharedMemorySize,
                         DSMEM_REQ);

    fused_kernel<<<TOTAL_CTAS, THREADS, DSMEM_REQ>>>(xyz, finit, cent, comb);
}